// round 13
// baseline (speedup 1.0000x reference)
#include <cuda_runtime.h>
#include <cuda_fp16.h>
#include <stdint.h>

// Problem constants
#define IC    384
#define OCC   384
#define NB    32
#define IH    64
#define IW    64
#define OH    32
#define OW    32
#define KTOT  (IC * 9)          // 3456
#define NWEI  (OCC * KTOT)      // 1327104
#define NTOT  (NB * OH * OW)    // 32768

// GEMM tiling: CTA = 64(M) x 128(N) x 32(K), 8 warps of 32x32, occupancy 3
#define BM    64
#define BN    128
#define BK    32
#define NKB   (KTOT / BK)       // 108
#define NTILE ((NTOT / BN) * 6) // 1536 logical tiles (6 m-tiles of 64)
#define GRID  444               // persistent: 3 CTAs x 148 SMs
#define THREADS 256
#define S     5                 // cp.async pipeline stages
#define ASTR  40                // halves per A smem row (80B, 16B-aligned, LDSM CF)
#define BSTR  136               // halves per B smem row (272B = 17 odd units, LDSM CF)
#define ABYTES (BM * ASTR * 2)  // 5120
#define BBYTES (BK * BSTR * 2)  // 8704
#define STAGE  (ABYTES + BBYTES)          // 13824
#define SMEM_TOTAL (S * STAGE)            // 69120 (x3 CTAs = 207KB/SM)

#define KWSZ ((size_t)NB * IC * 66 * 32)  // halves per kw plane
#define PREP_BLOCKS 49920                 // NB*IC*65*16/256
#define QUANT_BLOCKS 5184                 // ceil(NWEI/256)

// Scratch (device globals: allocation-free contract)
__device__ float  g_alpha;
__device__ float  g_part[256];
__device__ __half g_wq[(size_t)NKB * OCC * BK];  // [kb32][oc][32] ternary fp16
__device__ __half g_xq[3 * KWSZ];                // [kw][b][ic][row 0..65][ox 0..31]

// ---------------------------------------------------------------------------
// Stage 1: deterministic |w| reduction -> alpha
// ---------------------------------------------------------------------------
__global__ void abssum_part(const float* __restrict__ w) {
    __shared__ float sm[256];
    const int tid = threadIdx.x;
    float s = 0.f;
    for (int i = blockIdx.x * 256 + tid; i < NWEI; i += 256 * 256)
        s += fabsf(w[i]);
    sm[tid] = s;
    __syncthreads();
    #pragma unroll
    for (int o = 128; o > 0; o >>= 1) {
        if (tid < o) sm[tid] += sm[tid + o];
        __syncthreads();
    }
    if (tid == 0) g_part[blockIdx.x] = sm[0];
}

__global__ void abssum_fin() {
    __shared__ float sm[256];
    const int tid = threadIdx.x;
    sm[tid] = g_part[tid];
    __syncthreads();
    #pragma unroll
    for (int o = 128; o > 0; o >>= 1) {
        if (tid < o) sm[tid] += sm[tid + o];
        __syncthreads();
    }
    if (tid == 0) g_alpha = sm[0] / (float)NWEI;
}

// ---------------------------------------------------------------------------
// Stage 2 (merged): ternary quantize + x fp16 prep, one launch.
// ---------------------------------------------------------------------------
__global__ void prep_and_quant(const float* __restrict__ x,
                               const float* __restrict__ w) {
    const int tid = threadIdx.x;
    if (blockIdx.x < PREP_BLOCKS) {
        const int idx = blockIdx.x * 256 + tid;
        const int t = idx & 15;             // ox pair (2t, 2t+1)
        const int r = idx >> 4;             // row id over NB*IC*65
        const int iy = r % 65 - 1;          // -1..63
        const int bc = r / 65;              // b*IC + ic
        const size_t orow = ((size_t)bc * 66 + (iy + 1)) * 32 + 2 * t;

        __half2 h0, h1, h2;
        if (iy < 0) {
            h0 = h1 = h2 = __floats2half2_rn(0.f, 0.f);
        } else {
            const float* xr = x + ((size_t)bc * IH + iy) * IW;
            const float4 v = *reinterpret_cast<const float4*>(xr + 4 * t);
            const float prev = (t > 0) ? xr[4 * t - 1] : 0.f;
            h0 = __floats2half2_rn(prev, v.y);   // kw=0: ix = 2ox-1
            h1 = __floats2half2_rn(v.x,  v.z);   // kw=1: ix = 2ox
            h2 = __floats2half2_rn(v.y,  v.w);   // kw=2: ix = 2ox+1
        }
        *reinterpret_cast<__half2*>(g_xq + 0 * KWSZ + orow) = h0;
        *reinterpret_cast<__half2*>(g_xq + 1 * KWSZ + orow) = h1;
        *reinterpret_cast<__half2*>(g_xq + 2 * KWSZ + orow) = h2;
    } else {
        const int j = (blockIdx.x - PREP_BLOCKS) * 256 + tid;
        if (j >= NWEI) return;
        const float thr = 0.001f * g_alpha;
        const int oc  = j / KTOT;
        const int r   = j - oc * KTOT;
        const int tap = r / IC;
        const int ic  = r - tap * IC;
        const float wv = w[oc * KTOT + ic * 9 + tap];     // OIHW linear
        const float q = (wv > thr) ? 1.f : ((wv < -thr) ? -1.f : 0.f);
        const int kb = tap * 12 + (ic >> 5);
        g_wq[((size_t)kb * OCC + oc) * BK + (ic & 31)] = __float2half_rn(q);
    }
}

// ---------------------------------------------------------------------------
// Stage 3: persistent implicit-GEMM conv, 8 warps of 32x32, occ 3 (24 warps/SM)
// ---------------------------------------------------------------------------
__device__ __forceinline__ void cp16(uint32_t dst, const void* src) {
    asm volatile("cp.async.cg.shared.global [%0], [%1], 16;\n"
                 :: "r"(dst), "l"(src) : "memory");
}
__device__ __forceinline__ void ldsmA(uint32_t* f, uint32_t addr) {
    asm volatile("ldmatrix.sync.aligned.m8n8.x4.shared.b16 {%0,%1,%2,%3}, [%4];\n"
                 : "=r"(f[0]), "=r"(f[1]), "=r"(f[2]), "=r"(f[3]) : "r"(addr));
}
__device__ __forceinline__ void ldsmBT(uint32_t* f, uint32_t addr) {
    asm volatile("ldmatrix.sync.aligned.m8n8.x4.trans.shared.b16 {%0,%1,%2,%3}, [%4];\n"
                 : "=r"(f[0]), "=r"(f[1]), "=r"(f[2]), "=r"(f[3]) : "r"(addr));
}

__global__ __launch_bounds__(THREADS, 3)
void conv_mma10(const float* __restrict__ bias, float* __restrict__ out)
{
    extern __shared__ char smem_raw[];
    const uint32_t sbase = (uint32_t)__cvta_generic_to_shared(smem_raw);

    const int tid  = threadIdx.x;
    const int lane = tid & 31;
    const int wid  = tid >> 5;          // 0..7
    const int wm   = wid >> 2;          // 0..1 (m32 blocks)
    const int wn   = wid & 3;           // 0..3 (n32 blocks)

    // cp.async per-thread invariants
    // A: 1 chunk/thread: m = tid>>2 (0..63), c = tid&3
    const int am0 = tid >> 2, ac = tid & 3;
    const uint32_t adst0 = sbase + (uint32_t)(am0 * ASTR + ac * 8) * 2;
    // B: 2 chunks: slot = tid + 256j (j<2): kB = slot>>4 (0..31), nc = tid&15
    const int kB0 = tid >> 4, nc = tid & 15;
    const uint32_t bdst0 = sbase + (uint32_t)ABYTES + (uint32_t)(kB0 * BSTR + nc * 8) * 2;

    // ldmatrix per-lane invariants (32x32 warp tile)
    const int arow  = wm * 32 + ((lane >> 3) & 1) * 8 + (lane & 7);
    const int acol  = (lane >> 4) * 8;
    const int brow  = ((lane >> 3) & 1) * 8 + (lane & 7);
    const int bcolh = wn * 32 + (lane >> 4) * 8;

    const int g  = lane >> 2;
    const int tq = lane & 3;
    const float alpha = g_alpha;

    #pragma unroll 1
    for (int tile = blockIdx.x; tile < NTILE; tile += GRID) {
        const int m_tile = tile % 6;        // consecutive tiles share B slab in L2
        const int n_tile = tile / 6;
        const int oc0  = m_tile * BM;
        const int n0   = n_tile * BN;
        const int bimg = n0 >> 10;
        const int pos0 = n0 & 1023;
        const int oy0  = pos0 >> 5;

        const size_t aoff0 = (size_t)(oc0 + am0) * BK + ac * 8;
        const int    oyc   = oy0 + (nc >> 2);
        const size_t boff0 = ((size_t)(bimg * IC + kB0) * 66 + 2 * oyc) * 32 + (nc & 3) * 8;

        float acc[2][4][4];
        #pragma unroll
        for (int i = 0; i < 2; i++)
            #pragma unroll
            for (int j = 0; j < 4; j++)
                #pragma unroll
                for (int c = 0; c < 4; c++)
                    acc[i][j][c] = 0.f;

        auto issue = [&](int kb, int s) {
            const int tap = kb / 12;                 // 0..8
            const int icb = (kb - tap * 12) << 5;
            const int kh  = tap / 3;
            const int kw  = tap - kh * 3;
            const __half* wsrc = g_wq + (size_t)kb * (OCC * BK) + aoff0;
            const __half* xsrc = g_xq + (size_t)kw * KWSZ + boff0
                               + (size_t)icb * (66 * 32) + kh * 32;
            const uint32_t st = (uint32_t)(s * STAGE);
            cp16(adst0 + st, wsrc);                               // A: 64 rows
            cp16(bdst0 + st,                   xsrc);             // B k-rows 0..15
            cp16(bdst0 + st + (16 * BSTR * 2), xsrc + (size_t)16 * (66 * 32));
            asm volatile("cp.async.commit_group;\n" ::: "memory");
        };

        auto do_step = [&](uint32_t aB, uint32_t bB, int step) {
            uint32_t a[2][4], b[2][4];
            ldsmA(a[0], aB + (uint32_t)(((arow + 0) * ASTR) + step * 16 + acol) * 2);
            ldsmBT(b[0], bB + (uint32_t)((step * 16 + brow) * BSTR + bcolh) * 2);
            ldsmA(a[1], aB + (uint32_t)(((arow + 16) * ASTR) + step * 16 + acol) * 2);
            ldsmBT(b[1], bB + (uint32_t)((step * 16 + brow) * BSTR + bcolh + 16) * 2);
            #pragma unroll
            for (int ms = 0; ms < 2; ms++)
                #pragma unroll
                for (int ns = 0; ns < 4; ns++)
                    asm volatile(
                        "mma.sync.aligned.m16n8k16.row.col.f32.f16.f16.f32 "
                        "{%0,%1,%2,%3}, {%4,%5,%6,%7}, {%8,%9}, {%0,%1,%2,%3};\n"
                        : "+f"(acc[ms][ns][0]), "+f"(acc[ms][ns][1]),
                          "+f"(acc[ms][ns][2]), "+f"(acc[ms][ns][3])
                        : "r"(a[ms][0]), "r"(a[ms][1]), "r"(a[ms][2]), "r"(a[ms][3]),
                          "r"(b[ns >> 1][(ns & 1) * 2]),
                          "r"(b[ns >> 1][(ns & 1) * 2 + 1]));
        };

        auto compute = [&](int s) {
            const uint32_t aB = sbase + (uint32_t)(s * STAGE);
            const uint32_t bB = aB + (uint32_t)ABYTES;
            do_step(aB, bB, 0);
            do_step(aB, bB, 1);
        };

        // tile boundary: prologue below rewrites stages that straggler warps
        // of the previous tile may still be reading
        __syncthreads();

        // prologue: fill S-1 stages
        #pragma unroll
        for (int p = 0; p < S - 1; p++) issue(p, p);

        #pragma unroll 1
        for (int kb = 0; kb < NKB; kb++) {
            asm volatile("cp.async.wait_group %0;\n" :: "n"(S - 2) : "memory");
            __syncthreads();
            if (kb + (S - 1) < NKB)
                issue(kb + (S - 1), (kb + (S - 1)) % S);
            else
                asm volatile("cp.async.commit_group;\n" ::: "memory");  // keep count exact
            compute(kb % S);
        }

        // epilogue: out = alpha*acc + bias (regs->gmem only; no smem hazard)
        float* ob = out + (size_t)bimg * OCC * (OH * OW);
        #pragma unroll
        for (int ms = 0; ms < 2; ms++) {
            const int oc_a = oc0 + wm * 32 + ms * 16 + g;
            const int oc_b = oc_a + 8;
            const float ba = bias[oc_a];
            const float bc = bias[oc_b];
            #pragma unroll
            for (int ns = 0; ns < 4; ns++) {
                const int pcol = pos0 + wn * 32 + ns * 8 + tq * 2;
                float2 v0, v1;
                v0.x = alpha * acc[ms][ns][0] + ba;
                v0.y = alpha * acc[ms][ns][1] + ba;
                v1.x = alpha * acc[ms][ns][2] + bc;
                v1.y = alpha * acc[ms][ns][3] + bc;
                *reinterpret_cast<float2*>(ob + (size_t)oc_a * (OH * OW) + pcol) = v0;
                *reinterpret_cast<float2*>(ob + (size_t)oc_b * (OH * OW) + pcol) = v1;
            }
        }
    }
}

// ---------------------------------------------------------------------------
extern "C" void kernel_launch(void* const* d_in, const int* in_sizes, int n_in,
                              void* d_out, int out_size)
{
    (void)in_sizes; (void)n_in; (void)out_size;
    const float* x      = (const float*)d_in[0];
    const float* weight = (const float*)d_in[1];
    const float* bias   = (const float*)d_in[2];
    float* out = (float*)d_out;

    cudaFuncSetAttribute(conv_mma10, cudaFuncAttributeMaxDynamicSharedMemorySize, SMEM_TOTAL);

    abssum_part<<<256, 256>>>(weight);                        // launch 1
    abssum_fin<<<1, 256>>>();                                 // launch 2
    prep_and_quant<<<PREP_BLOCKS + QUANT_BLOCKS, 256>>>(x, weight);  // launch 3
    conv_mma10<<<GRID, THREADS, SMEM_TOTAL>>>(bias, out);     // launch 4 -> ncu captures this
}

// round 15
// speedup vs baseline: 1.1391x; 1.1391x over previous
#include <cuda_runtime.h>
#include <cuda_fp16.h>
#include <stdint.h>

// Problem constants
#define IC    384
#define OCC   384
#define NB    32
#define IH    64
#define IW    64
#define OH    32
#define OW    32
#define KTOT  (IC * 9)          // 3456
#define NWEI  (OCC * KTOT)      // 1327104
#define NTOT  (NB * OH * OW)    // 32768

// GEMM tiling: CTA = 128(M) x 128(N) x 32(K), 4 warps of 64x64, occupancy 3
#define BM    128
#define BN    128
#define BK    32
#define NKB   (KTOT / BK)       // 108
#define NNT   (NTOT / BN)       // 256 n-tiles
#define GRID  444               // persistent: 3 CTAs x 148 SMs
#define THREADS 128
#define S     3                 // cp.async stages (3 -> leaves ~58KB L1D for B sharing)
#define ASTR  40                // halves per A smem row (80B, 16B-aligned, LDSM CF)
#define BSTR  136               // halves per B smem row (272B = 17 odd units, LDSM CF)
#define ABYTES (BM * ASTR * 2)  // 10240
#define BBYTES (BK * BSTR * 2)  // 8704
#define STAGE  (ABYTES + BBYTES)          // 18944
#define SMEM_TOTAL (S * STAGE)            // 56832 (x3 CTAs = 170KB/SM, L1D ~58KB)

#define KWSZ ((size_t)NB * IC * 66 * 32)  // halves per kw plane
#define PREP_BLOCKS 24960                 // NB*IC*65*8/256
#define QUANT_BLOCKS 5184                 // ceil(NWEI/256)

// Scratch (device globals: allocation-free contract)
__device__ float  g_alpha;
__device__ float  g_part[256];
__device__ __half g_wq[(size_t)NKB * OCC * BK];  // [kb32][oc][32] ternary fp16
__device__ __half g_xq[3 * KWSZ];                // [kw][b][ic][row 0..65][ox 0..31]

// bit-cast helper (cuda_fp16.h has no __half2_as_uint)
__device__ __forceinline__ uint32_t h2u(__half2 h) {
    union { __half2 h; uint32_t u; } c;
    c.h = h;
    return c.u;
}

// ---------------------------------------------------------------------------
// Stage 1: deterministic |w| reduction -> alpha
// ---------------------------------------------------------------------------
__global__ void abssum_part(const float* __restrict__ w) {
    __shared__ float sm[256];
    const int tid = threadIdx.x;
    float s = 0.f;
    for (int i = blockIdx.x * 256 + tid; i < NWEI; i += 256 * 256)
        s += fabsf(w[i]);
    sm[tid] = s;
    __syncthreads();
    #pragma unroll
    for (int o = 128; o > 0; o >>= 1) {
        if (tid < o) sm[tid] += sm[tid + o];
        __syncthreads();
    }
    if (tid == 0) g_part[blockIdx.x] = sm[0];
}

__global__ void abssum_fin() {
    __shared__ float sm[256];
    const int tid = threadIdx.x;
    sm[tid] = g_part[tid];
    __syncthreads();
    #pragma unroll
    for (int o = 128; o > 0; o >>= 1) {
        if (tid < o) sm[tid] += sm[tid + o];
        __syncthreads();
    }
    if (tid == 0) g_alpha = sm[0] / (float)NWEI;
}

// ---------------------------------------------------------------------------
// Stage 2 (merged): ternary quantize + x fp16 prep (8B stores), one launch.
// ---------------------------------------------------------------------------
__global__ void prep_and_quant(const float* __restrict__ x,
                               const float* __restrict__ w) {
    const int tid = threadIdx.x;
    if (blockIdx.x < PREP_BLOCKS) {
        const int idx = blockIdx.x * 256 + tid;
        const int t = idx & 7;              // ox group 4t..4t+3
        const int r = idx >> 3;             // row id over NB*IC*65
        const int iy = r % 65 - 1;          // -1..63
        const int bc = r / 65;              // b*IC + ic
        const size_t orow = ((size_t)bc * 66 + (iy + 1)) * 32 + 4 * t;

        uint2 s0, s1, s2;
        if (iy < 0) {
            s0 = s1 = s2 = make_uint2(0u, 0u);
        } else {
            const float* xr = x + ((size_t)bc * IH + iy) * IW;
            const float4 v0 = *reinterpret_cast<const float4*>(xr + 8 * t);
            const float4 v1 = *reinterpret_cast<const float4*>(xr + 8 * t + 4);
            const float prev = (t > 0) ? xr[8 * t - 1] : 0.f;
            // kw=0: ix = 8t-1, 8t+1, 8t+3, 8t+5
            s0 = make_uint2(h2u(__floats2half2_rn(prev, v0.y)),
                            h2u(__floats2half2_rn(v0.w, v1.y)));
            // kw=1: ix = 8t, 8t+2, 8t+4, 8t+6
            s1 = make_uint2(h2u(__floats2half2_rn(v0.x, v0.z)),
                            h2u(__floats2half2_rn(v1.x, v1.z)));
            // kw=2: ix = 8t+1, 8t+3, 8t+5, 8t+7
            s2 = make_uint2(h2u(__floats2half2_rn(v0.y, v0.w)),
                            h2u(__floats2half2_rn(v1.y, v1.w)));
        }
        *reinterpret_cast<uint2*>(g_xq + 0 * KWSZ + orow) = s0;
        *reinterpret_cast<uint2*>(g_xq + 1 * KWSZ + orow) = s1;
        *reinterpret_cast<uint2*>(g_xq + 2 * KWSZ + orow) = s2;
    } else {
        const int j = (blockIdx.x - PREP_BLOCKS) * 256 + tid;
        if (j >= NWEI) return;
        const float thr = 0.001f * g_alpha;
        const int oc  = j / KTOT;
        const int r   = j - oc * KTOT;
        const int tap = r / IC;
        const int ic  = r - tap * IC;
        const float wv = w[oc * KTOT + ic * 9 + tap];     // OIHW linear
        const float q = (wv > thr) ? 1.f : ((wv < -thr) ? -1.f : 0.f);
        const int kb = tap * 12 + (ic >> 5);
        g_wq[((size_t)kb * OCC + oc) * BK + (ic & 31)] = __float2half_rn(q);
    }
}

// ---------------------------------------------------------------------------
// Stage 3: persistent implicit-GEMM conv, 4 warps of 64x64, occ 3.
//   Trio mapping: bids {b, b+148, b+296} co-reside on one SM (classic LUT
//   placement) and are assigned the SAME n-tile with m_tile = bid/148, so
//   their B loads (cp.async.ca) share L1.
// ---------------------------------------------------------------------------
__device__ __forceinline__ void cp16cg(uint32_t dst, const void* src) {
    asm volatile("cp.async.cg.shared.global [%0], [%1], 16;\n"
                 :: "r"(dst), "l"(src) : "memory");
}
__device__ __forceinline__ void cp16ca(uint32_t dst, const void* src) {
    asm volatile("cp.async.ca.shared.global [%0], [%1], 16;\n"
                 :: "r"(dst), "l"(src) : "memory");
}
__device__ __forceinline__ void ldsmA(uint32_t* f, uint32_t addr) {
    asm volatile("ldmatrix.sync.aligned.m8n8.x4.shared.b16 {%0,%1,%2,%3}, [%4];\n"
                 : "=r"(f[0]), "=r"(f[1]), "=r"(f[2]), "=r"(f[3]) : "r"(addr));
}
__device__ __forceinline__ void ldsmBT(uint32_t* f, uint32_t addr) {
    asm volatile("ldmatrix.sync.aligned.m8n8.x4.trans.shared.b16 {%0,%1,%2,%3}, [%4];\n"
                 : "=r"(f[0]), "=r"(f[1]), "=r"(f[2]), "=r"(f[3]) : "r"(addr));
}

__global__ __launch_bounds__(THREADS, 3)
void conv_mma11(const float* __restrict__ bias, float* __restrict__ out)
{
    extern __shared__ char smem_raw[];
    const uint32_t sbase = (uint32_t)__cvta_generic_to_shared(smem_raw);

    const int tid  = threadIdx.x;
    const int lane = tid & 31;
    const int wid  = tid >> 5;          // 0..3
    const int wm   = wid >> 1;          // 0..1
    const int wn   = wid & 1;           // 0..1

    // trio mapping
    const int m_tile = blockIdx.x / 148;      // 0..2, fixed per CTA
    const int trio   = blockIdx.x % 148;      // co-resident trio id
    const int oc0    = m_tile * BM;

    // cp.async per-thread invariants
    const int am0 = tid >> 2, ac = tid & 3;
    const uint32_t adst0 = sbase + (uint32_t)(am0 * ASTR + ac * 8) * 2;
    const int kB0 = tid >> 4, nc = tid & 15;
    const uint32_t bdst0 = sbase + (uint32_t)ABYTES + (uint32_t)(kB0 * BSTR + nc * 8) * 2;
    const size_t aoff0 = (size_t)(oc0 + am0) * BK + ac * 8;

    // ldmatrix per-lane invariants (64x64 warp tile)
    const int arow  = wm * 64 + ((lane >> 3) & 1) * 8 + (lane & 7);
    const int acol  = (lane >> 4) * 8;
    const int brow  = ((lane >> 3) & 1) * 8 + (lane & 7);
    const int bcolh = wn * 64 + (lane >> 4) * 8;

    const int g  = lane >> 2;
    const int tq = lane & 3;
    const float alpha = g_alpha;

    #pragma unroll 1
    for (int n_tile = trio; n_tile < NNT; n_tile += 148) {
        const int n0   = n_tile * BN;
        const int bimg = n0 >> 10;
        const int pos0 = n0 & 1023;
        const int oy0  = pos0 >> 5;

        const int    oyc   = oy0 + (nc >> 2);
        const size_t boff0 = ((size_t)(bimg * IC + kB0) * 66 + 2 * oyc) * 32 + (nc & 3) * 8;

        float acc[4][8][4];
        #pragma unroll
        for (int i = 0; i < 4; i++)
            #pragma unroll
            for (int j = 0; j < 8; j++)
                #pragma unroll
                for (int c = 0; c < 4; c++)
                    acc[i][j][c] = 0.f;

        auto issue = [&](int kb, int s) {
            const int tap = kb / 12;                 // 0..8
            const int icb = (kb - tap * 12) << 5;
            const int kh  = tap / 3;
            const int kw  = tap - kh * 3;
            const __half* wsrc = g_wq + (size_t)kb * (OCC * BK) + aoff0;
            const __half* xsrc = g_xq + (size_t)kw * KWSZ + boff0
                               + (size_t)icb * (66 * 32) + kh * 32;
            const uint32_t st = (uint32_t)(s * STAGE);
            #pragma unroll
            for (int j = 0; j < 4; j++)          // A rows am0 + 32j (L2-streamed)
                cp16cg(adst0 + st + j * (32 * ASTR * 2), wsrc + (size_t)j * (32 * BK));
            #pragma unroll
            for (int j = 0; j < 4; j++)          // B k-rows kB0 + 8j (L1-shared by trio)
                cp16ca(bdst0 + st + j * (8 * BSTR * 2), xsrc + (size_t)j * (8 * 66 * 32));
            asm volatile("cp.async.commit_group;\n" ::: "memory");
        };

        auto do_step = [&](uint32_t aB, uint32_t bB, int step) {
            uint32_t a[4][4];
            #pragma unroll
            for (int ms = 0; ms < 4; ms++)
                ldsmA(a[ms], aB + (uint32_t)(((arow + ms * 16) * ASTR)
                                             + step * 16 + acol) * 2);
            #pragma unroll
            for (int h = 0; h < 2; h++) {
                uint32_t b[2][4];
                #pragma unroll
                for (int nb = 0; nb < 2; nb++)
                    ldsmBT(b[nb], bB + (uint32_t)((step * 16 + brow) * BSTR
                                                  + bcolh + (h * 2 + nb) * 16) * 2);
                #pragma unroll
                for (int ms = 0; ms < 4; ms++)
                    #pragma unroll
                    for (int n2 = 0; n2 < 4; n2++)
                        asm volatile(
                            "mma.sync.aligned.m16n8k16.row.col.f32.f16.f16.f32 "
                            "{%0,%1,%2,%3}, {%4,%5,%6,%7}, {%8,%9}, {%0,%1,%2,%3};\n"
                            : "+f"(acc[ms][h * 4 + n2][0]), "+f"(acc[ms][h * 4 + n2][1]),
                              "+f"(acc[ms][h * 4 + n2][2]), "+f"(acc[ms][h * 4 + n2][3])
                            : "r"(a[ms][0]), "r"(a[ms][1]), "r"(a[ms][2]), "r"(a[ms][3]),
                              "r"(b[n2 >> 1][(n2 & 1) * 2]),
                              "r"(b[n2 >> 1][(n2 & 1) * 2 + 1]));
            }
        };

        auto compute = [&](int s) {
            const uint32_t aB = sbase + (uint32_t)(s * STAGE);
            const uint32_t bB = aB + (uint32_t)ABYTES;
            do_step(aB, bB, 0);
            do_step(aB, bB, 1);
        };

        // tile boundary: prologue below rewrites stages that straggler warps
        // of the previous tile may still be reading
        __syncthreads();

        // prologue: fill S-1 stages
        issue(0, 0); issue(1, 1);

        #pragma unroll 1
        for (int kb = 0; kb < NKB; kb++) {
            asm volatile("cp.async.wait_group %0;\n" :: "n"(S - 2) : "memory");
            __syncthreads();
            if (kb + (S - 1) < NKB)
                issue(kb + (S - 1), (kb + (S - 1)) % S);
            else
                asm volatile("cp.async.commit_group;\n" ::: "memory");  // keep count exact
            compute(kb % S);
        }

        // epilogue: out = alpha*acc + bias (regs->gmem only; no smem hazard)
        float* ob = out + (size_t)bimg * OCC * (OH * OW);
        #pragma unroll
        for (int ms = 0; ms < 4; ms++) {
            const int oc_a = oc0 + wm * 64 + ms * 16 + g;
            const int oc_b = oc_a + 8;
            const float ba = bias[oc_a];
            const float bc = bias[oc_b];
            #pragma unroll
            for (int ns = 0; ns < 8; ns++) {
                const int pcol = pos0 + wn * 64 + ns * 8 + tq * 2;
                float2 v0, v1;
                v0.x = alpha * acc[ms][ns][0] + ba;
                v0.y = alpha * acc[ms][ns][1] + ba;
                v1.x = alpha * acc[ms][ns][2] + bc;
                v1.y = alpha * acc[ms][ns][3] + bc;
                *reinterpret_cast<float2*>(ob + (size_t)oc_a * (OH * OW) + pcol) = v0;
                *reinterpret_cast<float2*>(ob + (size_t)oc_b * (OH * OW) + pcol) = v1;
            }
        }
    }
}

// ---------------------------------------------------------------------------
extern "C" void kernel_launch(void* const* d_in, const int* in_sizes, int n_in,
                              void* d_out, int out_size)
{
    (void)in_sizes; (void)n_in; (void)out_size;
    const float* x      = (const float*)d_in[0];
    const float* weight = (const float*)d_in[1];
    const float* bias   = (const float*)d_in[2];
    float* out = (float*)d_out;

    cudaFuncSetAttribute(conv_mma11, cudaFuncAttributeMaxDynamicSharedMemorySize, SMEM_TOTAL);

    abssum_part<<<256, 256>>>(weight);                        // launch 1
    abssum_fin<<<1, 256>>>();                                 // launch 2
    prep_and_quant<<<PREP_BLOCKS + QUANT_BLOCKS, 256>>>(x, weight);  // launch 3
    conv_mma11<<<GRID, THREADS, SMEM_TOTAL>>>(bias, out);     // launch 4 -> ncu captures this
}

// round 16
// speedup vs baseline: 1.1724x; 1.0292x over previous
#include <cuda_runtime.h>
#include <cuda_fp16.h>
#include <stdint.h>

// Problem constants
#define IC    384
#define OCC   384
#define NB    32
#define IH    64
#define IW    64
#define OH    32
#define OW    32
#define KTOT  (IC * 9)          // 3456
#define NWEI  (OCC * KTOT)      // 1327104
#define NTOT  (NB * OH * OW)    // 32768

// GEMM tiling: CTA = 128(M) x 128(N) x 32(K), 4 warps of 64x64, occupancy 3
#define BM    128
#define BN    128
#define BK    32
#define NKB   (KTOT / BK)       // 108
#define NTILE ((NTOT / BN) * 3) // 768 logical tiles
#define GRID  444               // persistent: 3 CTAs x 148 SMs
#define THREADS 128
#define S     4                 // cp.async pipeline stages
#define ASTR  40                // halves per A smem row (80B, 16B-aligned, LDSM CF)
#define BSTR  136               // halves per B smem row (272B = 17 odd units, LDSM CF)
#define ABYTES (BM * ASTR * 2)  // 10240
#define BBYTES (BK * BSTR * 2)  // 8704
#define STAGE  (ABYTES + BBYTES)          // 18944
#define SMEM_TOTAL (S * STAGE)            // 75776 (x3 CTAs = 222KB/SM)

#define KWSZ ((size_t)NB * IC * 66 * 32)  // halves per kw plane
#define PREP_BLOCKS 24960                 // NB*IC*65*8/256
#define QUANT_BLOCKS 5184                 // ceil(NWEI/256)

// Scratch (device globals: allocation-free contract)
__device__ float  g_alpha;
__device__ float  g_part[256];
__device__ __half g_wq[(size_t)NKB * OCC * BK];  // [kb32][oc][32] ternary fp16
__device__ __half g_xq[3 * KWSZ];                // [kw][b][ic][row 0..65][ox 0..31]

// bit-cast helper (cuda_fp16.h has no __half2_as_uint)
__device__ __forceinline__ uint32_t h2u(__half2 h) {
    union { __half2 h; uint32_t u; } c;
    c.h = h;
    return c.u;
}

// ---------------------------------------------------------------------------
// Stage 1: deterministic |w| reduction -> alpha
// ---------------------------------------------------------------------------
__global__ void abssum_part(const float* __restrict__ w) {
    __shared__ float sm[256];
    const int tid = threadIdx.x;
    float s = 0.f;
    for (int i = blockIdx.x * 256 + tid; i < NWEI; i += 256 * 256)
        s += fabsf(w[i]);
    sm[tid] = s;
    __syncthreads();
    #pragma unroll
    for (int o = 128; o > 0; o >>= 1) {
        if (tid < o) sm[tid] += sm[tid + o];
        __syncthreads();
    }
    if (tid == 0) g_part[blockIdx.x] = sm[0];
}

__global__ void abssum_fin() {
    __shared__ float sm[256];
    const int tid = threadIdx.x;
    sm[tid] = g_part[tid];
    __syncthreads();
    #pragma unroll
    for (int o = 128; o > 0; o >>= 1) {
        if (tid < o) sm[tid] += sm[tid + o];
        __syncthreads();
    }
    if (tid == 0) g_alpha = sm[0] / (float)NWEI;
}

// ---------------------------------------------------------------------------
// Stage 2 (merged): ternary quantize + x fp16 prep (8B stores), one launch.
// ---------------------------------------------------------------------------
__global__ void prep_and_quant(const float* __restrict__ x,
                               const float* __restrict__ w) {
    const int tid = threadIdx.x;
    if (blockIdx.x < PREP_BLOCKS) {
        const int idx = blockIdx.x * 256 + tid;
        const int t = idx & 7;              // ox group 4t..4t+3
        const int r = idx >> 3;             // row id over NB*IC*65
        const int iy = r % 65 - 1;          // -1..63
        const int bc = r / 65;              // b*IC + ic
        const size_t orow = ((size_t)bc * 66 + (iy + 1)) * 32 + 4 * t;

        uint2 s0, s1, s2;
        if (iy < 0) {
            s0 = s1 = s2 = make_uint2(0u, 0u);
        } else {
            const float* xr = x + ((size_t)bc * IH + iy) * IW;
            const float4 v0 = *reinterpret_cast<const float4*>(xr + 8 * t);
            const float4 v1 = *reinterpret_cast<const float4*>(xr + 8 * t + 4);
            const float prev = (t > 0) ? xr[8 * t - 1] : 0.f;
            // kw=0: ix = 8t-1, 8t+1, 8t+3, 8t+5
            s0 = make_uint2(h2u(__floats2half2_rn(prev, v0.y)),
                            h2u(__floats2half2_rn(v0.w, v1.y)));
            // kw=1: ix = 8t, 8t+2, 8t+4, 8t+6
            s1 = make_uint2(h2u(__floats2half2_rn(v0.x, v0.z)),
                            h2u(__floats2half2_rn(v1.x, v1.z)));
            // kw=2: ix = 8t+1, 8t+3, 8t+5, 8t+7
            s2 = make_uint2(h2u(__floats2half2_rn(v0.y, v0.w)),
                            h2u(__floats2half2_rn(v1.y, v1.w)));
        }
        *reinterpret_cast<uint2*>(g_xq + 0 * KWSZ + orow) = s0;
        *reinterpret_cast<uint2*>(g_xq + 1 * KWSZ + orow) = s1;
        *reinterpret_cast<uint2*>(g_xq + 2 * KWSZ + orow) = s2;
    } else {
        const int j = (blockIdx.x - PREP_BLOCKS) * 256 + tid;
        if (j >= NWEI) return;
        const float thr = 0.001f * g_alpha;
        const int oc  = j / KTOT;
        const int r   = j - oc * KTOT;
        const int tap = r / IC;
        const int ic  = r - tap * IC;
        const float wv = w[oc * KTOT + ic * 9 + tap];     // OIHW linear
        const float q = (wv > thr) ? 1.f : ((wv < -thr) ? -1.f : 0.f);
        const int kb = tap * 12 + (ic >> 5);
        g_wq[((size_t)kb * OCC + oc) * BK + (ic & 31)] = __float2half_rn(q);
    }
}

// ---------------------------------------------------------------------------
// Stage 3: persistent implicit-GEMM conv, 4 warps of 64x64, occ 3 (= R12 best)
// ---------------------------------------------------------------------------
__device__ __forceinline__ void cp16(uint32_t dst, const void* src) {
    asm volatile("cp.async.cg.shared.global [%0], [%1], 16;\n"
                 :: "r"(dst), "l"(src) : "memory");
}
__device__ __forceinline__ void ldsmA(uint32_t* f, uint32_t addr) {
    asm volatile("ldmatrix.sync.aligned.m8n8.x4.shared.b16 {%0,%1,%2,%3}, [%4];\n"
                 : "=r"(f[0]), "=r"(f[1]), "=r"(f[2]), "=r"(f[3]) : "r"(addr));
}
__device__ __forceinline__ void ldsmBT(uint32_t* f, uint32_t addr) {
    asm volatile("ldmatrix.sync.aligned.m8n8.x4.trans.shared.b16 {%0,%1,%2,%3}, [%4];\n"
                 : "=r"(f[0]), "=r"(f[1]), "=r"(f[2]), "=r"(f[3]) : "r"(addr));
}

__global__ __launch_bounds__(THREADS, 3)
void conv_mma12(const float* __restrict__ bias, float* __restrict__ out)
{
    extern __shared__ char smem_raw[];
    const uint32_t sbase = (uint32_t)__cvta_generic_to_shared(smem_raw);

    const int tid  = threadIdx.x;
    const int lane = tid & 31;
    const int wid  = tid >> 5;          // 0..3
    const int wm   = wid >> 1;          // 0..1
    const int wn   = wid & 1;           // 0..1

    // cp.async per-thread invariants (128 threads, 4 chunks per operand)
    const int am0 = tid >> 2, ac = tid & 3;
    const uint32_t adst0 = sbase + (uint32_t)(am0 * ASTR + ac * 8) * 2;
    const int kB0 = tid >> 4, nc = tid & 15;
    const uint32_t bdst0 = sbase + (uint32_t)ABYTES + (uint32_t)(kB0 * BSTR + nc * 8) * 2;

    // ldmatrix per-lane invariants (64x64 warp tile)
    const int arow  = wm * 64 + ((lane >> 3) & 1) * 8 + (lane & 7);
    const int acol  = (lane >> 4) * 8;
    const int brow  = ((lane >> 3) & 1) * 8 + (lane & 7);
    const int bcolh = wn * 64 + (lane >> 4) * 8;

    const int g  = lane >> 2;
    const int tq = lane & 3;
    const float alpha = g_alpha;

    #pragma unroll 1
    for (int tile = blockIdx.x; tile < NTILE; tile += GRID) {
        const int m_tile = tile % 3;        // consecutive tiles share B slab in L2
        const int n_tile = tile / 3;
        const int oc0  = m_tile * BM;
        const int n0   = n_tile * BN;
        const int bimg = n0 >> 10;
        const int pos0 = n0 & 1023;
        const int oy0  = pos0 >> 5;

        const size_t aoff0 = (size_t)(oc0 + am0) * BK + ac * 8;
        const int    oyc   = oy0 + (nc >> 2);
        const size_t boff0 = ((size_t)(bimg * IC + kB0) * 66 + 2 * oyc) * 32 + (nc & 3) * 8;

        float acc[4][8][4];
        #pragma unroll
        for (int i = 0; i < 4; i++)
            #pragma unroll
            for (int j = 0; j < 8; j++)
                #pragma unroll
                for (int c = 0; c < 4; c++)
                    acc[i][j][c] = 0.f;

        auto issue = [&](int kb, int s) {
            const int tap = kb / 12;                 // 0..8
            const int icb = (kb - tap * 12) << 5;
            const int kh  = tap / 3;
            const int kw  = tap - kh * 3;
            const __half* wsrc = g_wq + (size_t)kb * (OCC * BK) + aoff0;
            const __half* xsrc = g_xq + (size_t)kw * KWSZ + boff0
                               + (size_t)icb * (66 * 32) + kh * 32;
            const uint32_t st = (uint32_t)(s * STAGE);
            #pragma unroll
            for (int j = 0; j < 4; j++)          // A rows am0 + 32j
                cp16(adst0 + st + j * (32 * ASTR * 2), wsrc + (size_t)j * (32 * BK));
            #pragma unroll
            for (int j = 0; j < 4; j++)          // B k-rows kB0 + 8j
                cp16(bdst0 + st + j * (8 * BSTR * 2), xsrc + (size_t)j * (8 * 66 * 32));
            asm volatile("cp.async.commit_group;\n" ::: "memory");
        };

        auto do_step = [&](uint32_t aB, uint32_t bB, int step) {
            uint32_t a[4][4];
            #pragma unroll
            for (int ms = 0; ms < 4; ms++)
                ldsmA(a[ms], aB + (uint32_t)(((arow + ms * 16) * ASTR)
                                             + step * 16 + acol) * 2);
            // two n32-halves: 2 B-LDSM then 16 HMMA each; B regs stay at 8 live
            #pragma unroll
            for (int h = 0; h < 2; h++) {
                uint32_t b[2][4];
                #pragma unroll
                for (int nb = 0; nb < 2; nb++)
                    ldsmBT(b[nb], bB + (uint32_t)((step * 16 + brow) * BSTR
                                                  + bcolh + (h * 2 + nb) * 16) * 2);
                #pragma unroll
                for (int ms = 0; ms < 4; ms++)
                    #pragma unroll
                    for (int n2 = 0; n2 < 4; n2++)
                        asm volatile(
                            "mma.sync.aligned.m16n8k16.row.col.f32.f16.f16.f32 "
                            "{%0,%1,%2,%3}, {%4,%5,%6,%7}, {%8,%9}, {%0,%1,%2,%3};\n"
                            : "+f"(acc[ms][h * 4 + n2][0]), "+f"(acc[ms][h * 4 + n2][1]),
                              "+f"(acc[ms][h * 4 + n2][2]), "+f"(acc[ms][h * 4 + n2][3])
                            : "r"(a[ms][0]), "r"(a[ms][1]), "r"(a[ms][2]), "r"(a[ms][3]),
                              "r"(b[n2 >> 1][(n2 & 1) * 2]),
                              "r"(b[n2 >> 1][(n2 & 1) * 2 + 1]));
            }
        };

        auto compute = [&](int s) {
            const uint32_t aB = sbase + (uint32_t)(s * STAGE);
            const uint32_t bB = aB + (uint32_t)ABYTES;
            do_step(aB, bB, 0);
            do_step(aB, bB, 1);
        };

        // tile boundary: prologue below rewrites stages that straggler warps
        // of the previous tile may still be reading
        __syncthreads();

        // prologue: fill S-1 stages
        issue(0, 0); issue(1, 1); issue(2, 2);

        #pragma unroll 1
        for (int kb = 0; kb < NKB; kb++) {
            asm volatile("cp.async.wait_group %0;\n" :: "n"(S - 2) : "memory");
            __syncthreads();
            if (kb + (S - 1) < NKB)
                issue(kb + (S - 1), (kb + (S - 1)) % S);
            else
                asm volatile("cp.async.commit_group;\n" ::: "memory");  // keep count exact
            compute(kb % S);
        }

        // epilogue: out = alpha*acc + bias (regs->gmem only; no smem hazard)
        float* ob = out + (size_t)bimg * OCC * (OH * OW);
        #pragma unroll
        for (int ms = 0; ms < 4; ms++) {
            const int oc_a = oc0 + wm * 64 + ms * 16 + g;
            const int oc_b = oc_a + 8;
            const float ba = bias[oc_a];
            const float bc = bias[oc_b];
            #pragma unroll
            for (int ns = 0; ns < 8; ns++) {
                const int pcol = pos0 + wn * 64 + ns * 8 + tq * 2;
                float2 v0, v1;
                v0.x = alpha * acc[ms][ns][0] + ba;
                v0.y = alpha * acc[ms][ns][1] + ba;
                v1.x = alpha * acc[ms][ns][2] + bc;
                v1.y = alpha * acc[ms][ns][3] + bc;
                *reinterpret_cast<float2*>(ob + (size_t)oc_a * (OH * OW) + pcol) = v0;
                *reinterpret_cast<float2*>(ob + (size_t)oc_b * (OH * OW) + pcol) = v1;
            }
        }
    }
}

// ---------------------------------------------------------------------------
extern "C" void kernel_launch(void* const* d_in, const int* in_sizes, int n_in,
                              void* d_out, int out_size)
{
    (void)in_sizes; (void)n_in; (void)out_size;
    const float* x      = (const float*)d_in[0];
    const float* weight = (const float*)d_in[1];
    const float* bias   = (const float*)d_in[2];
    float* out = (float*)d_out;

    cudaFuncSetAttribute(conv_mma12, cudaFuncAttributeMaxDynamicSharedMemorySize, SMEM_TOTAL);

    abssum_part<<<256, 256>>>(weight);                        // launch 1
    abssum_fin<<<1, 256>>>();                                 // launch 2
    prep_and_quant<<<PREP_BLOCKS + QUANT_BLOCKS, 256>>>(x, weight);  // launch 3
    conv_mma12<<<GRID, THREADS, SMEM_TOTAL>>>(bias, out);     // launch 4 -> ncu captures this
}